// round 3
// baseline (speedup 1.0000x reference)
#include <cuda_runtime.h>
#include <stdint.h>

// Resolutions: floor(16 * growth^i) replicating numpy's float64 pipeline.
// Level 15 is an exact-boundary case: 16*growth^15 evaluates to 4095.9999...
// in float64 (accumulated rounding in log/div/exp/pow), so np.floor gives 4095.
__constant__ float c_res[16] = {
    16.f, 23.f, 33.f, 48.f, 70.f, 101.f, 147.f, 212.f,
    307.f, 445.f, 645.f, 933.f, 1351.f, 1955.f, 2830.f, 4095.f
};

#define HG_P2 2654435761u
#define HG_P3 805459861u
#define HG_MASK 0x7FFFFu   // T-1, T = 2^19

__global__ __launch_bounds__(256) void hashgrid_kernel(
    const float* __restrict__ x,
    const float* __restrict__ table,
    float2* __restrict__ out,
    int n_points)
{
    int t = blockIdx.x * blockDim.x + threadIdx.x;
    int p   = t >> 4;       // point index
    int lvl = t & 15;       // level index
    if (p >= n_points) return;

    // 16 lanes share the same point: these loads broadcast within the warp.
    float px = x[3 * p + 0];
    float py = x[3 * p + 1];
    float pz = x[3 * p + 2];

    float res = c_res[lvl];
    // Strict IEEE float32 RN, no fma contraction — matches reference ops.
    float sx = __fmul_rn(px, res);
    float sy = __fmul_rn(py, res);
    float sz = __fmul_rn(pz, res);
    float fx = floorf(sx);
    float fy = floorf(sy);
    float fz = floorf(sz);
    float wx = __fadd_rn(sx, -fx);
    float wy = __fadd_rn(sy, -fy);
    float wz = __fadd_rn(sz, -fz);

    int ix = (int)fx;
    int iy = (int)fy;
    int iz = (int)fz;

    // hash = (ix*1) ^ (iy*P2) ^ (iz*P3), masked to 19 bits. Exact integer math.
    uint32_t hx0 = (uint32_t)ix;
    uint32_t hx1 = hx0 + 1u;
    uint32_t hy0 = (uint32_t)iy * HG_P2;
    uint32_t hy1 = hy0 + HG_P2;
    uint32_t hz0 = (uint32_t)iz * HG_P3;
    uint32_t hz1 = hz0 + HG_P3;

    uint32_t i000 = (hx0 ^ hy0 ^ hz0) & HG_MASK;
    uint32_t i001 = (hx0 ^ hy0 ^ hz1) & HG_MASK;
    uint32_t i010 = (hx0 ^ hy1 ^ hz0) & HG_MASK;
    uint32_t i011 = (hx0 ^ hy1 ^ hz1) & HG_MASK;
    uint32_t i100 = (hx1 ^ hy0 ^ hz0) & HG_MASK;
    uint32_t i101 = (hx1 ^ hy0 ^ hz1) & HG_MASK;
    uint32_t i110 = (hx1 ^ hy1 ^ hz0) & HG_MASK;
    uint32_t i111 = (hx1 ^ hy1 ^ hz1) & HG_MASK;

    const float2* tab = (const float2*)table + ((uint32_t)lvl << 19);

    // Issue all 8 independent gathers back-to-back for MLP.
    float2 f000 = __ldg(tab + i000);
    float2 f001 = __ldg(tab + i001);
    float2 f010 = __ldg(tab + i010);
    float2 f011 = __ldg(tab + i011);
    float2 f100 = __ldg(tab + i100);
    float2 f101 = __ldg(tab + i101);
    float2 f110 = __ldg(tab + i110);
    float2 f111 = __ldg(tab + i111);

    float wx0 = __fadd_rn(1.0f, -wx), wx1 = wx;
    float wy0 = __fadd_rn(1.0f, -wy), wy1 = wy;
    float wz0 = __fadd_rn(1.0f, -wz), wz1 = wz;

    // w = (x_term * y_term) * z_term, left-associated, RN — matches reference.
    float w000 = __fmul_rn(__fmul_rn(wx0, wy0), wz0);
    float w001 = __fmul_rn(__fmul_rn(wx0, wy0), wz1);
    float w010 = __fmul_rn(__fmul_rn(wx0, wy1), wz0);
    float w011 = __fmul_rn(__fmul_rn(wx0, wy1), wz1);
    float w100 = __fmul_rn(__fmul_rn(wx1, wy0), wz0);
    float w101 = __fmul_rn(__fmul_rn(wx1, wy0), wz1);
    float w110 = __fmul_rn(__fmul_rn(wx1, wy1), wz0);
    float w111 = __fmul_rn(__fmul_rn(wx1, wy1), wz1);

    // Accumulate in reference corner order with separate RN mul + add (no FMA).
    float a0 = 0.0f, a1 = 0.0f;
    a0 = __fadd_rn(a0, __fmul_rn(f000.x, w000));  a1 = __fadd_rn(a1, __fmul_rn(f000.y, w000));
    a0 = __fadd_rn(a0, __fmul_rn(f001.x, w001));  a1 = __fadd_rn(a1, __fmul_rn(f001.y, w001));
    a0 = __fadd_rn(a0, __fmul_rn(f010.x, w010));  a1 = __fadd_rn(a1, __fmul_rn(f010.y, w010));
    a0 = __fadd_rn(a0, __fmul_rn(f011.x, w011));  a1 = __fadd_rn(a1, __fmul_rn(f011.y, w011));
    a0 = __fadd_rn(a0, __fmul_rn(f100.x, w100));  a1 = __fadd_rn(a1, __fmul_rn(f100.y, w100));
    a0 = __fadd_rn(a0, __fmul_rn(f101.x, w101));  a1 = __fadd_rn(a1, __fmul_rn(f101.y, w101));
    a0 = __fadd_rn(a0, __fmul_rn(f110.x, w110));  a1 = __fadd_rn(a1, __fmul_rn(f110.y, w110));
    a0 = __fadd_rn(a0, __fmul_rn(f111.x, w111));  a1 = __fadd_rn(a1, __fmul_rn(f111.y, w111));

    // 16 consecutive lanes (same point) write contiguous 128B: fully coalesced.
    out[p * 16 + lvl] = make_float2(a0, a1);
}

extern "C" void kernel_launch(void* const* d_in, const int* in_sizes, int n_in,
                              void* d_out, int out_size)
{
    // Defensive input-order resolution: x (N*3 = 3.1M floats) is the smaller
    // buffer; hash_table (T*L*F = 16.7M floats) is the larger one.
    const float* a = (const float*)d_in[0];
    const float* b = (const float*)d_in[1];
    int sa = in_sizes[0], sb = in_sizes[1];

    const float* x;
    const float* table;
    int x_elems;
    if (sa <= sb) { x = a; table = b; x_elems = sa; }
    else          { x = b; table = a; x_elems = sb; }

    float2* out = (float2*)d_out;

    int n_points = x_elems / 3;
    int total = n_points * 16;
    int block = 256;
    int grid = (total + block - 1) / block;
    hashgrid_kernel<<<grid, block>>>(x, table, out, n_points);
}